// round 3
// baseline (speedup 1.0000x reference)
#include <cuda_runtime.h>

// DynamicRoutingLayer: capsule dynamic routing, B=256 N=512 E=64 O=64 K=8, 3 softmax passes.
// Key identities: cc_t = cc_0 + delta_t[b,k,n];  delta_t[b,k,n] = dot(priors[b,n,:], Vcum_t[b,k,:])
// => never materialize updated cc; recompute delta on the fly from tiny Vcum.
// HBM-bound: floor = 3 reads of cc (268MB) + priors traffic ~ 1.0 GB total.

#define BB 256
#define NN 512
#define EE 64
#define OO 64
#define KK 8
#define NCHUNK 4
#define NPC (NN / NCHUNK)   // 128 n-rows per block

// Scratch: __device__ globals (no cudaMalloc allowed).
__device__ float g_priors[(size_t)BB * NN * OO];          // 33.5 MB
__device__ float g_zpart[(size_t)BB * NCHUNK * KK * OO];  // 2 MB partial z per n-chunk
__device__ float g_vcum[(size_t)BB * KK * OO];            // 0.5 MB cumulative squashed v

// ---------------------------------------------------------------------------
__global__ void init_vcum_k() {
    int i = blockIdx.x * blockDim.x + threadIdx.x;
    if (i < BB * KK * OO) g_vcum[i] = 0.0f;
}

// ---------------------------------------------------------------------------
// priors[b,n,o] = sum_e emb[b,n,e] * S[e,o].  64 rows x 64 cols per block,
// 4x4 register micro-tile per thread, S + emb tile staged in smem.
__global__ __launch_bounds__(256) void gemm_priors_k(const float* __restrict__ emb,
                                                     const float* __restrict__ Sm) {
    __shared__ float sS[64 * 64];      // [e][o]
    __shared__ float sE[64 * 65];      // [r][e], padded -> conflict-free
    const int tid = threadIdx.x;
    const size_t rowBase = (size_t)blockIdx.x * 64;   // flattened (b*N + n)

    for (int i = tid; i < 4096; i += 256) sS[i] = Sm[i];
    for (int i = tid; i < 4096; i += 256) sE[(i >> 6) * 65 + (i & 63)] = emb[rowBase * EE + i];
    __syncthreads();

    const int tc = tid & 15, tr = tid >> 4;
    const int r0 = tr * 4, o0 = tc * 4;
    float a[4][4];
#pragma unroll
    for (int i = 0; i < 4; i++)
#pragma unroll
        for (int j = 0; j < 4; j++) a[i][j] = 0.0f;

#pragma unroll 8
    for (int e = 0; e < 64; e++) {
        float4 sv = *(const float4*)(sS + e * 64 + o0);
#pragma unroll
        for (int i = 0; i < 4; i++) {
            float av = sE[(r0 + i) * 65 + e];
            a[i][0] += av * sv.x;
            a[i][1] += av * sv.y;
            a[i][2] += av * sv.z;
            a[i][3] += av * sv.w;
        }
    }
#pragma unroll
    for (int i = 0; i < 4; i++) {
        float4 v = make_float4(a[i][0], a[i][1], a[i][2], a[i][3]);
        *(float4*)(g_priors + (rowBase + r0 + i) * OO + o0) = v;
    }
}

// ---------------------------------------------------------------------------
// One softmax/routing pass: z[b,k,o] = sum_n softmax_k(cc0[b,k,n,o] + delta[b,k,n]) * p[b,n,o]
// delta[b,k,n] = dot(p[b,n,:], Vcum[b,k,:]) computed on the fly (warp shfl reduce).
// Softmax over K=8 is entirely per-thread (lane owns o = 2*lane, 2*lane+1).
// grid (NCHUNK, B), 256 threads = 8 warps x 16 n-rows each. Deterministic fixed-order reduce.
__global__ __launch_bounds__(256) void routing_pass_k(const float* __restrict__ cc0) {
    __shared__ float sV[KK * OO];        // Vcum for this b (2 KB)
    __shared__ float sred[8][KK * OO];   // per-warp partial z (16 KB)

    const int b = blockIdx.y;
    const int chunk = blockIdx.x;
    const int tid = threadIdx.x;
    const int warp = tid >> 5;
    const int lane = tid & 31;

    for (int i = tid; i < KK * OO; i += 256) sV[i] = g_vcum[b * KK * OO + i];
    __syncthreads();

    float vc0[KK], vc1[KK];
#pragma unroll
    for (int k = 0; k < KK; k++) {
        vc0[k] = sV[k * OO + 2 * lane];
        vc1[k] = sV[k * OO + 2 * lane + 1];
    }

    float acc0[KK], acc1[KK];
#pragma unroll
    for (int k = 0; k < KK; k++) { acc0[k] = 0.0f; acc1[k] = 0.0f; }

    const size_t ccBase = (size_t)b * KK * NN * OO;

    for (int nn = warp; nn < NPC; nn += 8) {
        const int n = chunk * NPC + nn;

        // --- front-batch the global loads: p row + 8 k-strided cc rows (MLP ~9) ---
        const float2 p = *(const float2*)(g_priors + ((size_t)b * NN + n) * OO + 2 * lane);
        const float* cp = cc0 + ccBase + (size_t)n * OO + 2 * lane;
        float2 c[KK];
#pragma unroll
        for (int k = 0; k < KK; k++) c[k] = *(const float2*)(cp + (size_t)k * NN * OO);

        // delta[k] = dot over o of p * Vcum  (lane partial + warp butterfly reduce)
        float d[KK];
#pragma unroll
        for (int k = 0; k < KK; k++) d[k] = p.x * vc0[k] + p.y * vc1[k];
#pragma unroll
        for (int off = 16; off > 0; off >>= 1) {
#pragma unroll
            for (int k = 0; k < KK; k++) d[k] += __shfl_xor_sync(0xffffffffu, d[k], off);
        }

        float s0[KK], s1[KK];
#pragma unroll
        for (int k = 0; k < KK; k++) {
            s0[k] = c[k].x + d[k];
            s1[k] = c[k].y + d[k];
        }

        // softmax over k (per-thread, max-stabilized), fused multiply by p, accumulate
        float m0 = s0[0], m1 = s1[0];
#pragma unroll
        for (int k = 1; k < KK; k++) { m0 = fmaxf(m0, s0[k]); m1 = fmaxf(m1, s1[k]); }
        float e0[KK], e1[KK];
        float sum0 = 0.0f, sum1 = 0.0f;
#pragma unroll
        for (int k = 0; k < KK; k++) {
            e0[k] = __expf(s0[k] - m0); sum0 += e0[k];
            e1[k] = __expf(s1[k] - m1); sum1 += e1[k];
        }
        const float w0 = p.x * __frcp_rn(sum0);
        const float w1 = p.y * __frcp_rn(sum1);
#pragma unroll
        for (int k = 0; k < KK; k++) {
            acc0[k] += e0[k] * w0;
            acc1[k] += e1[k] * w1;
        }
    }

    // deterministic cross-warp reduction via smem tree
#pragma unroll
    for (int k = 0; k < KK; k++) {
        sred[warp][k * OO + 2 * lane] = acc0[k];
        sred[warp][k * OO + 2 * lane + 1] = acc1[k];
    }
    __syncthreads();
#pragma unroll 2
    for (int s = tid; s < KK * OO; s += 256) {
        float t = 0.0f;
#pragma unroll
        for (int w = 0; w < 8; w++) t += sred[w][s];
        g_zpart[(size_t)(b * NCHUNK + chunk) * KK * OO + s] = t;
    }
}

// ---------------------------------------------------------------------------
// squash(z) with z = sum over 4 n-chunk partials (fixed order). One warp per (b,k).
__device__ __forceinline__ void squash_core(int bk, int lane, float& v0, float& v1) {
    const int b = bk >> 3, k = bk & 7;
    float z0 = 0.0f, z1 = 0.0f;
#pragma unroll
    for (int c = 0; c < NCHUNK; c++) {
        const float* p = g_zpart + (size_t)((b * NCHUNK + c) * KK + k) * OO;
        z0 += p[2 * lane];
        z1 += p[2 * lane + 1];
    }
    float sq = z0 * z0 + z1 * z1;
#pragma unroll
    for (int off = 16; off > 0; off >>= 1) sq += __shfl_xor_sync(0xffffffffu, sq, off);
    const float f = (sq / (1.0f + sq)) * rsqrtf(sq + 1e-9f);
    v0 = f * z0;
    v1 = f * z1;
}

__global__ void squash_acc_k() {
    const int bk = blockIdx.x, lane = threadIdx.x;
    float v0, v1;
    squash_core(bk, lane, v0, v1);
    g_vcum[bk * OO + 2 * lane] += v0;
    g_vcum[bk * OO + 2 * lane + 1] += v1;
}

__global__ void squash_out_k(float* __restrict__ out) {
    const int bk = blockIdx.x, lane = threadIdx.x;
    float v0, v1;
    squash_core(bk, lane, v0, v1);
    out[bk * OO + 2 * lane] = v0;
    out[bk * OO + 2 * lane + 1] = v1;
}

// ---------------------------------------------------------------------------
extern "C" void kernel_launch(void* const* d_in, const int* in_sizes, int n_in,
                              void* d_out, int out_size) {
    const float* emb = (const float*)d_in[0];   // (B,N,E) fp32
    const float* Sm  = (const float*)d_in[1];   // (E,O)   fp32
    const float* cc  = (const float*)d_in[2];   // (B,K,N,O) fp32
    float* out = (float*)d_out;                 // (B,K,O) fp32

    init_vcum_k<<<(BB * KK * OO + 255) / 256, 256>>>();
    gemm_priors_k<<<BB * NN / 64, 256>>>(emb, Sm);

    dim3 rg(NCHUNK, BB);
    // iter 1 + iter 2: softmax pass -> squash -> accumulate into Vcum
    routing_pass_k<<<rg, 256>>>(cc);
    squash_acc_k<<<BB * KK, 32>>>();
    routing_pass_k<<<rg, 256>>>(cc);
    squash_acc_k<<<BB * KK, 32>>>();
    // final: softmax pass -> squash -> output
    routing_pass_k<<<rg, 256>>>(cc);
    squash_out_k<<<BB * KK, 32>>>(out);
}